// round 5
// baseline (speedup 1.0000x reference)
#include <cuda_runtime.h>
#include <cuda_bf16.h>

// ---------------------------------------------------------------------------
// IterativeEmbeddingModel: 2 iterations of
//   emb <- concat(emb@T1, seg_sum(emb[col],row)@T2, seg_sum_anti(...)@T3)
// R5:
//  - GEMM: k-pair dot-product FFMA2 (no dup MOVs). A loaded as natural ull
//    k-pairs (broadcast), B pre-packed in smem as [96 kpairs][64 cols] ulls,
//    lane tx owns cols {tx,tx+16,tx+32,tx+48} (conflict-free LDS64).
//    24 issue slots per 32 FMA-pipe cycles -> FMA-bound (was 22/16 issue-bound).
//    16 NAMED scalar accumulators (no arrays -> no local-mem demotion).
//  - CSR build forked onto cudaStreamPerThread (R2 proved capture-legal and
//    neutral; now GEMM1 is long enough to hide it).
// ---------------------------------------------------------------------------

#define NMAX 50000
#define EMAX 400000
#define DIM  192
#define PP   64

typedef unsigned long long ull;

// Scratch (device globals; no allocation APIs allowed)
__device__ int   g_count[2 * NMAX];
__device__ int   g_cursor[2 * NMAX];
__device__ int   g_rowstart[2 * (NMAX + 1)];
__device__ int   g_blocksum[2 * 128];
__device__ int   g_cols[2 * EMAX];
__device__ float g_emb1[(size_t)NMAX * DIM];   // iteration-1 output
__device__ float g_Y[(size_t)NMAX * 128];      // [Y2 | Y3] per row

// ---- packed f32x2 helpers -------------------------------------------------
__device__ __forceinline__ ull pack2(float lo, float hi) {
    ull r; asm("mov.b64 %0, {%1, %2};" : "=l"(r) : "f"(lo), "f"(hi)); return r;
}
__device__ __forceinline__ void fma2(ull &c, ull a, ull b) {
    asm("fma.rn.f32x2 %0, %1, %2, %0;" : "+l"(c) : "l"(a), "l"(b));
}
__device__ __forceinline__ float2 unpack2(ull v) {
    float2 f; asm("mov.b64 {%0, %1}, %2;" : "=f"(f.x), "=f"(f.y) : "l"(v)); return f;
}

// ---- CSR build ------------------------------------------------------------
__global__ void zero_counts_kernel() {
    int i = blockIdx.x * blockDim.x + threadIdx.x;
    if (i < 2 * NMAX) g_count[i] = 0;
}

__global__ void hist_kernel(const int* __restrict__ e0, const int* __restrict__ e1, int nE) {
    int i = blockIdx.x * blockDim.x + threadIdx.x;
    if (i >= 2 * nE) return;
    int l = (i < nE) ? 0 : 1;
    const int* p = l ? e1 : e0;
    int e = l ? (i - nE) : i;
    int d = p[e];
    atomicAdd(&g_count[l * NMAX + d], 1);
}

__global__ void scan_partial_kernel(int n) {
    __shared__ int warp_sums[16];
    int l = blockIdx.y;
    int i = blockIdx.x * 512 + threadIdx.x;
    int lane = threadIdx.x & 31;
    int w = threadIdx.x >> 5;
    int v = (i < n) ? g_count[l * NMAX + i] : 0;
    int s = v;
#pragma unroll
    for (int o = 1; o < 32; o <<= 1) {
        int t = __shfl_up_sync(0xFFFFFFFFu, s, o);
        if (lane >= o) s += t;
    }
    if (lane == 31) warp_sums[w] = s;
    __syncthreads();
    if (w == 0) {
        int ws = (lane < 16) ? warp_sums[lane] : 0;
#pragma unroll
        for (int o = 1; o < 16; o <<= 1) {
            int t = __shfl_up_sync(0xFFFFFFFFu, ws, o);
            if (lane >= o) ws += t;
        }
        if (lane < 16) warp_sums[lane] = ws;
    }
    __syncthreads();
    int base = (w > 0) ? warp_sums[w - 1] : 0;
    if (i < n) g_rowstart[l * (NMAX + 1) + i] = base + s - v;
    if (threadIdx.x == 511) g_blocksum[l * 128 + blockIdx.x] = base + s;
}

__global__ void add_offsets_kernel(int n, int nb) {
    int l = blockIdx.y;
    int i = blockIdx.x * blockDim.x + threadIdx.x;
    __shared__ int sP;
    if (threadIdx.x < 32) {
        int myblk = blockIdx.x >> 1;
        int s = 0;
        for (int b = threadIdx.x; b < myblk; b += 32) s += g_blocksum[l * 128 + b];
#pragma unroll
        for (int o = 16; o; o >>= 1) s += __shfl_xor_sync(0xFFFFFFFFu, s, o);
        if (threadIdx.x == 0) sP = s;
    }
    if (blockIdx.x == 0 && threadIdx.x >= 32 && threadIdx.x < 64) {
        int lane = threadIdx.x - 32;
        int s = 0;
        for (int b = lane; b < nb; b += 32) s += g_blocksum[l * 128 + b];
#pragma unroll
        for (int o = 16; o; o >>= 1) s += __shfl_xor_sync(0xFFFFFFFFu, s, o);
        if (lane == 0) g_rowstart[l * (NMAX + 1) + n] = s;
    }
    __syncthreads();
    if (i < n) {
        g_rowstart[l * (NMAX + 1) + i] += sP;
        g_cursor[l * NMAX + i] = 0;
    }
}

__global__ void fill_kernel(const int* __restrict__ e0, const int* __restrict__ e1, int nE) {
    int i = blockIdx.x * blockDim.x + threadIdx.x;
    if (i >= 2 * nE) return;
    int l = (i < nE) ? 0 : 1;
    const int* p = l ? e1 : e0;
    int e = l ? (i - nE) : i;
    int d = p[e];
    int c = p[nE + e];
    int pos = g_rowstart[l * (NMAX + 1) + d] + atomicAdd(&g_cursor[l * NMAX + d], 1);
    g_cols[l * EMAX + pos] = c;
}

// ---- GEMM: Y = A @ [T0|T1|T2]; T0 part straight to dst cols[0:64] ---------
// As: [64][196] fp32 (rows 16B-aligned). B2: [96 kpairs][64 cols] ull,
// pre-packed (B[2kp][c], B[2kp+1][c]). 4x4 microtile, 16 named accumulators.
#define AS_STRIDE 196
#define GEMM_SMEM_BYTES ((64 * AS_STRIDE) * 4 + 96 * 64 * 8)

__global__ __launch_bounds__(256, 2)
void gemm_kernel(const float* __restrict__ A,
                 const float* __restrict__ T0,
                 const float* __restrict__ T1,
                 const float* __restrict__ T2,
                 float* __restrict__ dst,   // n x 192 (cols 0:64 written here)
                 float* __restrict__ Y,     // n x 128 (Y2|Y3)
                 int n)
{
    extern __shared__ float sm[];
    float* As = sm;                                // [64][196]
    ull*   B2 = (ull*)(sm + 64 * AS_STRIDE);       // [96][64]
    const int tid = threadIdx.x;
    const int tx = tid & 15;         // col lane: owns cols tx+16j
    const int ty = tid >> 4;         // row group (4 rows)
    const int rowBase = blockIdx.x * 64;

    // Load A tile (64 x 192), zero-pad OOB rows
    for (int f = tid; f < 64 * 48; f += 256) {
        int r = f / 48, c4 = f % 48;
        int gr = rowBase + r;
        float4 v = make_float4(0.f, 0.f, 0.f, 0.f);
        if (gr < n) v = *(const float4*)(A + (size_t)gr * DIM + c4 * 4);
        *(float4*)(As + r * AS_STRIDE + c4 * 4) = v;
    }

    const float* Tarr[3] = {T0, T1, T2};
#pragma unroll
    for (int t = 0; t < 3; ++t) {
        __syncthreads();
        const float* Tt = Tarr[t];
        // Pack theta into k-pair ulls: B2[kp*64 + c] = (T[2kp][c], T[2kp+1][c])
        for (int f = tid; f < 96 * 64; f += 256) {
            int kp = f >> 6, c = f & 63;
            float lo = Tt[(2 * kp) * 64 + c];
            float hi = Tt[(2 * kp + 1) * 64 + c];
            B2[f] = pack2(lo, hi);
        }
        __syncthreads();

        ull c00 = 0, c01 = 0, c02 = 0, c03 = 0;
        ull c10 = 0, c11 = 0, c12 = 0, c13 = 0;
        ull c20 = 0, c21 = 0, c22 = 0, c23 = 0;
        ull c30 = 0, c31 = 0, c32 = 0, c33 = 0;
        const float* Ap = As + (ty * 4) * AS_STRIDE;
        const ull*   Bp = B2 + tx;
#pragma unroll 4
        for (int kp = 0; kp < 96; kp++) {
            ull a0 = *(const ull*)(Ap + 0 * AS_STRIDE + 2 * kp);
            ull a1 = *(const ull*)(Ap + 1 * AS_STRIDE + 2 * kp);
            ull a2 = *(const ull*)(Ap + 2 * AS_STRIDE + 2 * kp);
            ull a3 = *(const ull*)(Ap + 3 * AS_STRIDE + 2 * kp);
            ull b0 = Bp[kp * 64 + 0];
            ull b1 = Bp[kp * 64 + 16];
            ull b2 = Bp[kp * 64 + 32];
            ull b3 = Bp[kp * 64 + 48];
            fma2(c00, a0, b0); fma2(c01, a0, b1); fma2(c02, a0, b2); fma2(c03, a0, b3);
            fma2(c10, a1, b0); fma2(c11, a1, b1); fma2(c12, a1, b2); fma2(c13, a1, b3);
            fma2(c20, a2, b0); fma2(c21, a2, b1); fma2(c22, a2, b2); fma2(c23, a2, b3);
            fma2(c30, a3, b0); fma2(c31, a3, b1); fma2(c32, a3, b2); fma2(c33, a3, b3);
        }

        // Epilogue: scalar = lane-sum of each k-pair accumulator.
#define EPI(CIJ, i, j)                                                          \
        {                                                                       \
            int gr = rowBase + ty * 4 + (i);                                    \
            if (gr < n) {                                                       \
                float2 p = unpack2(CIJ);                                        \
                float v = p.x + p.y;                                            \
                if (t == 0) dst[(size_t)gr * DIM + tx + 16 * (j)] = v;          \
                else        Y[(size_t)gr * 128 + (t - 1) * 64 + tx + 16 * (j)] = v; \
            }                                                                   \
        }
        EPI(c00, 0, 0) EPI(c01, 0, 1) EPI(c02, 0, 2) EPI(c03, 0, 3)
        EPI(c10, 1, 0) EPI(c11, 1, 1) EPI(c12, 1, 2) EPI(c13, 1, 3)
        EPI(c20, 2, 0) EPI(c21, 2, 1) EPI(c22, 2, 2) EPI(c23, 2, 3)
        EPI(c30, 3, 0) EPI(c31, 3, 1) EPI(c32, 3, 2) EPI(c33, 3, 3)
#undef EPI
    }
}

// ---- Aggregation: warp per node, atomic-free CSR gather -------------------
__global__ void agg_kernel(const float* __restrict__ Y, float* __restrict__ dst, int n)
{
    int gw = (blockIdx.x * blockDim.x + threadIdx.x) >> 5;
    int lane = threadIdx.x & 31;
    if (gw >= n) return;
#pragma unroll
    for (int l = 0; l < 2; ++l) {
        const int* rs = g_rowstart + l * (NMAX + 1);
        const int* cs = g_cols + l * EMAX;
        int s = __ldg(rs + gw);
        int e = __ldg(rs + gw + 1);
        const float* Yb = Y + l * 64 + lane * 2;
        float ax = 0.f, ay = 0.f;
        int j = s;
        for (; j + 4 <= e; j += 4) {
            int c0 = cs[j], c1 = cs[j + 1], c2 = cs[j + 2], c3 = cs[j + 3];
            float2 v0 = *(const float2*)(Yb + (size_t)c0 * 128);
            float2 v1 = *(const float2*)(Yb + (size_t)c1 * 128);
            float2 v2 = *(const float2*)(Yb + (size_t)c2 * 128);
            float2 v3 = *(const float2*)(Yb + (size_t)c3 * 128);
            ax += (v0.x + v1.x) + (v2.x + v3.x);
            ay += (v0.y + v1.y) + (v2.y + v3.y);
        }
        for (; j < e; ++j) {
            float2 v = *(const float2*)(Yb + (size_t)cs[j] * 128);
            ax += v.x; ay += v.y;
        }
        float2 o = make_float2(ax, ay);
        *(float2*)(dst + (size_t)gw * DIM + 64 + l * 64 + lane * 2) = o;
    }
}

// ---------------------------------------------------------------------------
extern "C" void kernel_launch(void* const* d_in, const int* in_sizes, int n_in,
                              void* d_out, int out_size)
{
    const float* emb = (const float*)d_in[0];
    const float* t1  = (const float*)d_in[1];
    const float* t2  = (const float*)d_in[2];
    const float* t3  = (const float*)d_in[3];
    const int*   e0  = (const int*)d_in[4];
    const int*   e1  = (const int*)d_in[5];

    int n  = in_sizes[0] / DIM;
    int nE = in_sizes[4] / 2;
    float* out = (float*)d_out;

    void *p_emb1_v, *p_Y_v;
    cudaGetSymbolAddress(&p_emb1_v, g_emb1);
    cudaGetSymbolAddress(&p_Y_v, g_Y);
    float* p_emb1 = (float*)p_emb1_v;
    float* p_Y    = (float*)p_Y_v;

    cudaFuncSetAttribute(gemm_kernel, cudaFuncAttributeMaxDynamicSharedMemorySize,
                         GEMM_SMEM_BYTES);

    // Fork/join events (DisableTiming). Leaked intentionally (2 calls total).
    cudaEvent_t evFork, evJoin;
    cudaEventCreateWithFlags(&evFork, cudaEventDisableTiming);
    cudaEventCreateWithFlags(&evJoin, cudaEventDisableTiming);
    cudaStream_t side = cudaStreamPerThread;

    cudaEventRecord(evFork, 0);
    cudaStreamWaitEvent(side, evFork, 0);

    // --- CSR build on side stream (overlaps GEMM1) ---
    int nb = (n + 511) / 512;
    zero_counts_kernel<<<(2 * NMAX + 255) / 256, 256, 0, side>>>();
    hist_kernel<<<(2 * nE + 255) / 256, 256, 0, side>>>(e0, e1, nE);
    dim3 gscan(nb, 2);
    scan_partial_kernel<<<gscan, 512, 0, side>>>(n);
    dim3 goff((n + 255) / 256, 2);
    add_offsets_kernel<<<goff, 256, 0, side>>>(n, nb);
    fill_kernel<<<(2 * nE + 255) / 256, 256, 0, side>>>(e0, e1, nE);
    cudaEventRecord(evJoin, side);

    int gemm_blocks = (n + 63) / 64;
    int agg_blocks = (n * 32 + 255) / 256;

    // --- iteration 1 (GEMM1 concurrent with CSR build) ---
    gemm_kernel<<<gemm_blocks, 256, GEMM_SMEM_BYTES>>>(emb, t1, t2, t3, p_emb1, p_Y, n);
    cudaStreamWaitEvent(0, evJoin, 0);   // agg needs the CSR
    agg_kernel<<<agg_blocks, 256>>>(p_Y, p_emb1, n);

    // --- iteration 2 ---
    gemm_kernel<<<gemm_blocks, 256, GEMM_SMEM_BYTES>>>(p_emb1, t1, t2, t3, out, p_Y, n);
    agg_kernel<<<agg_blocks, 256>>>(p_Y, out, n);
}

// round 7
// speedup vs baseline: 1.4905x; 1.4905x over previous
#include <cuda_runtime.h>
#include <cuda_bf16.h>
#include <cstdint>

// ---------------------------------------------------------------------------
// IterativeEmbeddingModel: 2 iterations of
//   emb <- concat(emb@T1, seg_sum(emb[col],row)@T2, seg_sum_anti(...)@T3)
// R7: tcgen05 unavailable (ptxas target is base sm_100, no 'a' features).
//     GEMM uses portable mma.sync.m16n8k16 bf16 (sm_80+) with split-bf16
//     3-term (AhiBhi + AhiBlo + AloBhi): ~2^-17 precision, tolerance 1e-3.
//     BM=128/CTA, 8 warps, warp = m16 x n64 (8 tiles), named float4 accums.
//     A converted to bf16 hi/lo in-kernel (padded smem, conflict-free);
//     thetas converted once to transposed bf16 hi/lo device globals.
// ---------------------------------------------------------------------------

#define NMAX 50000
#define EMAX 400000
#define DIM  192
#define PP   64

// Scratch (device globals; no allocation APIs allowed)
__device__ int      g_count[2 * NMAX];
__device__ int      g_cursor[2 * NMAX];
__device__ int      g_rowstart[2 * (NMAX + 1)];
__device__ int      g_blocksum[2 * 128];
__device__ int      g_cols[2 * EMAX];
__device__ float    g_emb1[(size_t)NMAX * DIM];   // iteration-1 output
__device__ float    g_Y[(size_t)NMAX * 128];      // [Y2 | Y3] per row
__device__ uint32_t g_Bh32[3 * 64 * 96];          // thetas bf16-hi, [t][n][k] pairs
__device__ uint32_t g_Bl32[3 * 64 * 96];          // thetas bf16-lo

// ---- CSR build ------------------------------------------------------------
__global__ void zero_counts_kernel() {
    int i = blockIdx.x * blockDim.x + threadIdx.x;
    if (i < 2 * NMAX) g_count[i] = 0;
}

__global__ void hist_kernel(const int* __restrict__ e0, const int* __restrict__ e1, int nE) {
    int i = blockIdx.x * blockDim.x + threadIdx.x;
    if (i >= 2 * nE) return;
    int l = (i < nE) ? 0 : 1;
    const int* p = l ? e1 : e0;
    int e = l ? (i - nE) : i;
    int d = p[e];
    atomicAdd(&g_count[l * NMAX + d], 1);
}

__global__ void scan_partial_kernel(int n) {
    __shared__ int warp_sums[16];
    int l = blockIdx.y;
    int i = blockIdx.x * 512 + threadIdx.x;
    int lane = threadIdx.x & 31;
    int w = threadIdx.x >> 5;
    int v = (i < n) ? g_count[l * NMAX + i] : 0;
    int s = v;
#pragma unroll
    for (int o = 1; o < 32; o <<= 1) {
        int t = __shfl_up_sync(0xFFFFFFFFu, s, o);
        if (lane >= o) s += t;
    }
    if (lane == 31) warp_sums[w] = s;
    __syncthreads();
    if (w == 0) {
        int ws = (lane < 16) ? warp_sums[lane] : 0;
#pragma unroll
        for (int o = 1; o < 16; o <<= 1) {
            int t = __shfl_up_sync(0xFFFFFFFFu, ws, o);
            if (lane >= o) ws += t;
        }
        if (lane < 16) warp_sums[lane] = ws;
    }
    __syncthreads();
    int base = (w > 0) ? warp_sums[w - 1] : 0;
    if (i < n) g_rowstart[l * (NMAX + 1) + i] = base + s - v;
    if (threadIdx.x == 511) g_blocksum[l * 128 + blockIdx.x] = base + s;
}

__global__ void add_offsets_kernel(int n, int nb) {
    int l = blockIdx.y;
    int i = blockIdx.x * blockDim.x + threadIdx.x;
    __shared__ int sP;
    if (threadIdx.x < 32) {
        int myblk = blockIdx.x >> 1;
        int s = 0;
        for (int b = threadIdx.x; b < myblk; b += 32) s += g_blocksum[l * 128 + b];
#pragma unroll
        for (int o = 16; o; o >>= 1) s += __shfl_xor_sync(0xFFFFFFFFu, s, o);
        if (threadIdx.x == 0) sP = s;
    }
    if (blockIdx.x == 0 && threadIdx.x >= 32 && threadIdx.x < 64) {
        int lane = threadIdx.x - 32;
        int s = 0;
        for (int b = lane; b < nb; b += 32) s += g_blocksum[l * 128 + b];
#pragma unroll
        for (int o = 16; o; o >>= 1) s += __shfl_xor_sync(0xFFFFFFFFu, s, o);
        if (lane == 0) g_rowstart[l * (NMAX + 1) + n] = s;
    }
    __syncthreads();
    if (i < n) {
        g_rowstart[l * (NMAX + 1) + i] += sP;
        g_cursor[l * NMAX + i] = 0;
    }
}

__global__ void fill_kernel(const int* __restrict__ e0, const int* __restrict__ e1, int nE) {
    int i = blockIdx.x * blockDim.x + threadIdx.x;
    if (i >= 2 * nE) return;
    int l = (i < nE) ? 0 : 1;
    const int* p = l ? e1 : e0;
    int e = l ? (i - nE) : i;
    int d = p[e];
    int c = p[nE + e];
    int pos = g_rowstart[l * (NMAX + 1) + d] + atomicAdd(&g_cursor[l * NMAX + d], 1);
    g_cols[l * EMAX + pos] = c;
}

// ---- Theta conversion (once): fp32 [192,64] -> bf16 hi/lo [t][n][192] -----
__global__ void convert_theta_kernel(const float* __restrict__ t1,
                                     const float* __restrict__ t2,
                                     const float* __restrict__ t3) {
    int i = blockIdx.x * blockDim.x + threadIdx.x;   // over 3*64*96 u32 pairs
    if (i >= 3 * 64 * 96) return;
    int tt = i / 6144;
    int rem = i % 6144;
    int nn = rem / 96;
    int k2 = rem % 96;
    const float* T = (tt == 0) ? t1 : (tt == 1) ? t2 : t3;
    float x0 = T[(size_t)(2 * k2) * 64 + nn];
    float x1 = T[(size_t)(2 * k2 + 1) * 64 + nn];
    __nv_bfloat162 hh = __floats2bfloat162_rn(x0, x1);
    float r0 = x0 - __low2float(hh);
    float r1 = x1 - __high2float(hh);
    __nv_bfloat162 ll = __floats2bfloat162_rn(r0, r1);
    g_Bh32[i] = *(uint32_t*)&hh;
    g_Bl32[i] = *(uint32_t*)&ll;
}

// ---- mma.sync GEMM --------------------------------------------------------
// Per CTA: rows [rowBase, rowBase+128), all 192 output cols (3 thetas).
// smem layout (bf16 elems, row stride 200 => conflict-free frag loads):
//   Ah[128][200] | Al[128][200] | Bh[64][200] | Bl[64][200]
#define A_STRIDE 200
#define OFF_AH 0
#define OFF_AL 51200
#define OFF_BH 102400
#define OFF_BL 128000
#define GEMM_SMEM_BYTES 153600

#define MMA(C, A0, A1, A2, A3, B0, B1)                                  \
    asm("mma.sync.aligned.m16n8k16.row.col.f32.bf16.bf16.f32 "          \
        "{%0,%1,%2,%3}, {%4,%5,%6,%7}, {%8,%9}, {%0,%1,%2,%3};"         \
        : "+f"(C.x), "+f"(C.y), "+f"(C.z), "+f"(C.w)                    \
        : "r"(A0), "r"(A1), "r"(A2), "r"(A3), "r"(B0), "r"(B1))

__global__ __launch_bounds__(256, 1)
void gemm_kernel(const float* __restrict__ A,
                 float* __restrict__ dst,   // n x 192 (theta0 -> cols 0:64)
                 float* __restrict__ Y,     // n x 128 (theta1|theta2)
                 int n)
{
    extern __shared__ char smem[];
    uint16_t* Ah16 = (uint16_t*)(smem + OFF_AH);
    uint16_t* Al16 = (uint16_t*)(smem + OFF_AL);
    uint16_t* Bh16 = (uint16_t*)(smem + OFF_BH);
    uint16_t* Bl16 = (uint16_t*)(smem + OFF_BL);
    uint32_t* Ah32 = (uint32_t*)Ah16;
    uint32_t* Al32 = (uint32_t*)Al16;
    uint32_t* Bh32 = (uint32_t*)Bh16;
    uint32_t* Bl32 = (uint32_t*)Bl16;

    const int tid = threadIdx.x;
    const int w = tid >> 5;
    const int lane = tid & 31;
    const int g = lane >> 2;       // fragment group row
    const int q = lane & 3;        // fragment thread-in-group
    const int rowBase = blockIdx.x * 128;

    // ---- Convert A rows to bf16 hi/lo in smem (coalesced, conflict-free) --
    for (int f = tid; f < 128 * 96; f += 256) {
        int r = f / 96, k2 = f % 96;
        int gr = rowBase + r;
        float2 v = make_float2(0.f, 0.f);
        if (gr < n) v = *(const float2*)(A + (size_t)gr * DIM + 2 * k2);
        __nv_bfloat162 hh = __floats2bfloat162_rn(v.x, v.y);
        float r0 = v.x - __low2float(hh);
        float r1 = v.y - __high2float(hh);
        __nv_bfloat162 ll = __floats2bfloat162_rn(r0, r1);
        Ah32[r * 100 + k2] = *(uint32_t*)&hh;
        Al32[r * 100 + k2] = *(uint32_t*)&ll;
    }

    const int ar0 = (w * 16 + g) * A_STRIDE;  // A elem offset of frag row g
    const int brg = g * A_STRIDE;             // B elem offset of frag col g
    const int row0 = rowBase + w * 16 + g;
    const int row1 = row0 + 8;

#pragma unroll
    for (int tt = 0; tt < 3; ++tt) {
        __syncthreads();   // previous theta's B readers done (and A ready)
        {
            const uint32_t* gh = g_Bh32 + tt * 6144;
            const uint32_t* gl = g_Bl32 + tt * 6144;
            for (int f = tid; f < 64 * 96; f += 256) {
                int nn = f / 96, k2 = f % 96;
                Bh32[nn * 100 + k2] = gh[f];
                Bl32[nn * 100 + k2] = gl[f];
            }
        }
        __syncthreads();

        float4 c0 = make_float4(0.f, 0.f, 0.f, 0.f), c1 = c0, c2 = c0, c3 = c0;
        float4 c4 = c0, c5 = c0, c6 = c0, c7 = c0;

#pragma unroll 1
        for (int ks = 0; ks < 12; ++ks) {
            const int k0 = ks * 16 + 2 * q;
            const uint16_t* aa = Ah16 + ar0 + k0;
            uint32_t ah0 = *(const uint32_t*)(aa);
            uint32_t ah1 = *(const uint32_t*)(aa + 8 * A_STRIDE);
            uint32_t ah2 = *(const uint32_t*)(aa + 8);
            uint32_t ah3 = *(const uint32_t*)(aa + 8 * A_STRIDE + 8);
            const uint16_t* al = Al16 + ar0 + k0;
            uint32_t al0 = *(const uint32_t*)(al);
            uint32_t al1 = *(const uint32_t*)(al + 8 * A_STRIDE);
            uint32_t al2 = *(const uint32_t*)(al + 8);
            uint32_t al3 = *(const uint32_t*)(al + 8 * A_STRIDE + 8);

#define DO_TILE(C, J)                                                         \
            {                                                                 \
                const uint16_t* bh = Bh16 + (J) * 8 * A_STRIDE + brg + k0;    \
                uint32_t bh0 = *(const uint32_t*)(bh);                        \
                uint32_t bh1 = *(const uint32_t*)(bh + 8);                    \
                const uint16_t* bl = Bl16 + (J) * 8 * A_STRIDE + brg + k0;    \
                uint32_t bl0 = *(const uint32_t*)(bl);                        \
                uint32_t bl1 = *(const uint32_t*)(bl + 8);                    \
                MMA(C, ah0, ah1, ah2, ah3, bh0, bh1);                         \
                MMA(C, ah0, ah1, ah2, ah3, bl0, bl1);                         \
                MMA(C, al0, al1, al2, al3, bh0, bh1);                         \
            }
            DO_TILE(c0, 0) DO_TILE(c1, 1) DO_TILE(c2, 2) DO_TILE(c3, 3)
            DO_TILE(c4, 4) DO_TILE(c5, 5) DO_TILE(c6, 6) DO_TILE(c7, 7)
#undef DO_TILE
        }

        // ---- Epilogue for this theta ----
        float* outp = (tt == 0) ? dst : Y;
        const int ostr = (tt == 0) ? DIM : 128;
        const int cb = (tt == 2) ? 64 : 0;
#define ST_TILE(C, J)                                                         \
        {                                                                     \
            int col = cb + (J) * 8 + 2 * q;                                   \
            if (row0 < n)                                                     \
                *(float2*)(outp + (size_t)row0 * ostr + col) =                \
                    make_float2(C.x, C.y);                                    \
            if (row1 < n)                                                     \
                *(float2*)(outp + (size_t)row1 * ostr + col) =                \
                    make_float2(C.z, C.w);                                    \
        }
        ST_TILE(c0, 0) ST_TILE(c1, 1) ST_TILE(c2, 2) ST_TILE(c3, 3)
        ST_TILE(c4, 4) ST_TILE(c5, 5) ST_TILE(c6, 6) ST_TILE(c7, 7)
#undef ST_TILE
    }
}

// ---- Aggregation: warp per node, atomic-free CSR gather -------------------
__global__ void agg_kernel(const float* __restrict__ Y, float* __restrict__ dst, int n)
{
    int gw = (blockIdx.x * blockDim.x + threadIdx.x) >> 5;
    int lane = threadIdx.x & 31;
    if (gw >= n) return;
#pragma unroll
    for (int l = 0; l < 2; ++l) {
        const int* rs = g_rowstart + l * (NMAX + 1);
        const int* cs = g_cols + l * EMAX;
        int s = __ldg(rs + gw);
        int e = __ldg(rs + gw + 1);
        const float* Yb = Y + l * 64 + lane * 2;
        float ax = 0.f, ay = 0.f;
        int j = s;
        for (; j + 4 <= e; j += 4) {
            int c0 = cs[j], c1 = cs[j + 1], c2 = cs[j + 2], c3 = cs[j + 3];
            float2 v0 = *(const float2*)(Yb + (size_t)c0 * 128);
            float2 v1 = *(const float2*)(Yb + (size_t)c1 * 128);
            float2 v2 = *(const float2*)(Yb + (size_t)c2 * 128);
            float2 v3 = *(const float2*)(Yb + (size_t)c3 * 128);
            ax += (v0.x + v1.x) + (v2.x + v3.x);
            ay += (v0.y + v1.y) + (v2.y + v3.y);
        }
        for (; j < e; ++j) {
            float2 v = *(const float2*)(Yb + (size_t)cs[j] * 128);
            ax += v.x; ay += v.y;
        }
        float2 o = make_float2(ax, ay);
        *(float2*)(dst + (size_t)gw * DIM + 64 + l * 64 + lane * 2) = o;
    }
}

// ---------------------------------------------------------------------------
extern "C" void kernel_launch(void* const* d_in, const int* in_sizes, int n_in,
                              void* d_out, int out_size)
{
    const float* emb = (const float*)d_in[0];
    const float* t1  = (const float*)d_in[1];
    const float* t2  = (const float*)d_in[2];
    const float* t3  = (const float*)d_in[3];
    const int*   e0  = (const int*)d_in[4];
    const int*   e1  = (const int*)d_in[5];

    int n  = in_sizes[0] / DIM;
    int nE = in_sizes[4] / 2;
    float* out = (float*)d_out;

    void *p_emb1_v, *p_Y_v;
    cudaGetSymbolAddress(&p_emb1_v, g_emb1);
    cudaGetSymbolAddress(&p_Y_v, g_Y);
    float* p_emb1 = (float*)p_emb1_v;
    float* p_Y    = (float*)p_Y_v;

    cudaFuncSetAttribute(gemm_kernel, cudaFuncAttributeMaxDynamicSharedMemorySize,
                         GEMM_SMEM_BYTES);

    int nb = (n + 511) / 512;
    int gemm_blocks = (n + 127) / 128;
    int agg_blocks = (n * 32 + 255) / 256;

    // gemm1 at launch slot #4 (the slot ncu captures) for profiling.
    zero_counts_kernel<<<(2 * NMAX + 255) / 256, 256>>>();                 // 1
    hist_kernel<<<(2 * nE + 255) / 256, 256>>>(e0, e1, nE);                // 2
    convert_theta_kernel<<<(3 * 64 * 96 + 255) / 256, 256>>>(t1, t2, t3);  // 3
    gemm_kernel<<<gemm_blocks, 256, GEMM_SMEM_BYTES>>>(emb, p_emb1, p_Y, n); // 4
    dim3 gscan(nb, 2);
    scan_partial_kernel<<<gscan, 512>>>(n);                                // 5
    dim3 goff((n + 255) / 256, 2);
    add_offsets_kernel<<<goff, 256>>>(n, nb);                              // 6
    fill_kernel<<<(2 * nE + 255) / 256, 256>>>(e0, e1, nE);                // 7
    agg_kernel<<<agg_blocks, 256>>>(p_Y, p_emb1, n);                       // 8
    gemm_kernel<<<gemm_blocks, 256, GEMM_SMEM_BYTES>>>(p_emb1, out, p_Y, n); // 9
    agg_kernel<<<agg_blocks, 256>>>(p_Y, out, n);                          // 10
}

// round 8
// speedup vs baseline: 1.7361x; 1.1648x over previous
#include <cuda_runtime.h>
#include <cuda_bf16.h>
#include <cstdint>

// ---------------------------------------------------------------------------
// IterativeEmbeddingModel: 2 iterations of
//   emb <- concat(emb@T1, seg_sum(emb[col],row)@T2, seg_sum_anti(...)@T3)
// R8 (vs R7, which profiled gemm at 78us, tensor=25.5%, occ=12.4%):
//  - GEMM: 512 threads / 16 warps per CTA (was 256/8): occ 12.4 -> 25%.
//    Warp = m16 x n32 (4 n-tiles).
//  - ldmatrix.x4 for all fragments: per-warp per-kstep issues 36 -> 18.
//  Same split-bf16 3-term math (rel_err ~6e-6, tolerance 1e-3).
// ---------------------------------------------------------------------------

#define NMAX 50000
#define EMAX 400000
#define DIM  192
#define PP   64

// Scratch (device globals; no allocation APIs allowed)
__device__ int      g_count[2 * NMAX];
__device__ int      g_cursor[2 * NMAX];
__device__ int      g_rowstart[2 * (NMAX + 1)];
__device__ int      g_blocksum[2 * 128];
__device__ int      g_cols[2 * EMAX];
__device__ float    g_emb1[(size_t)NMAX * DIM];   // iteration-1 output
__device__ float    g_Y[(size_t)NMAX * 128];      // [Y2 | Y3] per row
__device__ uint32_t g_Bh32[3 * 64 * 96];          // thetas bf16-hi, [t][n][k] pairs
__device__ uint32_t g_Bl32[3 * 64 * 96];          // thetas bf16-lo

__device__ __forceinline__ uint32_t smem_to_u32(const void* p) {
    uint32_t a;
    asm("{ .reg .u64 t; cvta.to.shared.u64 t, %1; cvt.u32.u64 %0, t; }"
        : "=r"(a) : "l"(p));
    return a;
}

// ---- CSR build ------------------------------------------------------------
__global__ void zero_counts_kernel() {
    int i = blockIdx.x * blockDim.x + threadIdx.x;
    if (i < 2 * NMAX) g_count[i] = 0;
}

__global__ void hist_kernel(const int* __restrict__ e0, const int* __restrict__ e1, int nE) {
    int i = blockIdx.x * blockDim.x + threadIdx.x;
    if (i >= 2 * nE) return;
    int l = (i < nE) ? 0 : 1;
    const int* p = l ? e1 : e0;
    int e = l ? (i - nE) : i;
    int d = p[e];
    atomicAdd(&g_count[l * NMAX + d], 1);
}

__global__ void scan_partial_kernel(int n) {
    __shared__ int warp_sums[16];
    int l = blockIdx.y;
    int i = blockIdx.x * 512 + threadIdx.x;
    int lane = threadIdx.x & 31;
    int w = threadIdx.x >> 5;
    int v = (i < n) ? g_count[l * NMAX + i] : 0;
    int s = v;
#pragma unroll
    for (int o = 1; o < 32; o <<= 1) {
        int t = __shfl_up_sync(0xFFFFFFFFu, s, o);
        if (lane >= o) s += t;
    }
    if (lane == 31) warp_sums[w] = s;
    __syncthreads();
    if (w == 0) {
        int ws = (lane < 16) ? warp_sums[lane] : 0;
#pragma unroll
        for (int o = 1; o < 16; o <<= 1) {
            int t = __shfl_up_sync(0xFFFFFFFFu, ws, o);
            if (lane >= o) ws += t;
        }
        if (lane < 16) warp_sums[lane] = ws;
    }
    __syncthreads();
    int base = (w > 0) ? warp_sums[w - 1] : 0;
    if (i < n) g_rowstart[l * (NMAX + 1) + i] = base + s - v;
    if (threadIdx.x == 511) g_blocksum[l * 128 + blockIdx.x] = base + s;
}

__global__ void add_offsets_kernel(int n, int nb) {
    int l = blockIdx.y;
    int i = blockIdx.x * blockDim.x + threadIdx.x;
    __shared__ int sP;
    if (threadIdx.x < 32) {
        int myblk = blockIdx.x >> 1;
        int s = 0;
        for (int b = threadIdx.x; b < myblk; b += 32) s += g_blocksum[l * 128 + b];
#pragma unroll
        for (int o = 16; o; o >>= 1) s += __shfl_xor_sync(0xFFFFFFFFu, s, o);
        if (threadIdx.x == 0) sP = s;
    }
    if (blockIdx.x == 0 && threadIdx.x >= 32 && threadIdx.x < 64) {
        int lane = threadIdx.x - 32;
        int s = 0;
        for (int b = lane; b < nb; b += 32) s += g_blocksum[l * 128 + b];
#pragma unroll
        for (int o = 16; o; o >>= 1) s += __shfl_xor_sync(0xFFFFFFFFu, s, o);
        if (lane == 0) g_rowstart[l * (NMAX + 1) + n] = s;
    }
    __syncthreads();
    if (i < n) {
        g_rowstart[l * (NMAX + 1) + i] += sP;
        g_cursor[l * NMAX + i] = 0;
    }
}

__global__ void fill_kernel(const int* __restrict__ e0, const int* __restrict__ e1, int nE) {
    int i = blockIdx.x * blockDim.x + threadIdx.x;
    if (i >= 2 * nE) return;
    int l = (i < nE) ? 0 : 1;
    const int* p = l ? e1 : e0;
    int e = l ? (i - nE) : i;
    int d = p[e];
    int c = p[nE + e];
    int pos = g_rowstart[l * (NMAX + 1) + d] + atomicAdd(&g_cursor[l * NMAX + d], 1);
    g_cols[l * EMAX + pos] = c;
}

// ---- Theta conversion (once): fp32 [192,64] -> bf16 hi/lo [t][n][192] -----
__global__ void convert_theta_kernel(const float* __restrict__ t1,
                                     const float* __restrict__ t2,
                                     const float* __restrict__ t3) {
    int i = blockIdx.x * blockDim.x + threadIdx.x;   // over 3*64*96 u32 pairs
    if (i >= 3 * 64 * 96) return;
    int tt = i / 6144;
    int rem = i % 6144;
    int nn = rem / 96;
    int k2 = rem % 96;
    const float* T = (tt == 0) ? t1 : (tt == 1) ? t2 : t3;
    float x0 = T[(size_t)(2 * k2) * 64 + nn];
    float x1 = T[(size_t)(2 * k2 + 1) * 64 + nn];
    __nv_bfloat162 hh = __floats2bfloat162_rn(x0, x1);
    float r0 = x0 - __low2float(hh);
    float r1 = x1 - __high2float(hh);
    __nv_bfloat162 ll = __floats2bfloat162_rn(r0, r1);
    g_Bh32[i] = *(uint32_t*)&hh;
    g_Bl32[i] = *(uint32_t*)&ll;
}

// ---- mma.sync GEMM --------------------------------------------------------
// Per CTA: rows [rowBase, rowBase+128), all 192 output cols (3 thetas).
// 512 threads / 16 warps: warp (w&7) -> m16 row group, (w>>3) -> n half (32).
// smem (bf16 elems, row stride 200 = 4 banks -> conflict-free ldmatrix):
//   Ah[128][200] | Al[128][200] | Bh[64][200] | Bl[64][200]
#define A_STRIDE 200
#define OFF_AH 0
#define OFF_AL 51200
#define OFF_BH 102400
#define OFF_BL 128000
#define GEMM_SMEM_BYTES 153600

#define MMA(C, A0, A1, A2, A3, B0, B1)                                  \
    asm("mma.sync.aligned.m16n8k16.row.col.f32.bf16.bf16.f32 "          \
        "{%0,%1,%2,%3}, {%4,%5,%6,%7}, {%8,%9}, {%0,%1,%2,%3};"         \
        : "+f"(C.x), "+f"(C.y), "+f"(C.z), "+f"(C.w)                    \
        : "r"(A0), "r"(A1), "r"(A2), "r"(A3), "r"(B0), "r"(B1))

#define LDMX4(R0, R1, R2, R3, ADDR)                                     \
    asm volatile("ldmatrix.sync.aligned.m8n8.x4.shared.b16 "            \
                 "{%0,%1,%2,%3}, [%4];"                                 \
                 : "=r"(R0), "=r"(R1), "=r"(R2), "=r"(R3) : "r"(ADDR))

__global__ __launch_bounds__(512, 1)
void gemm_kernel(const float* __restrict__ A,
                 float* __restrict__ dst,   // n x 192 (theta0 -> cols 0:64)
                 float* __restrict__ Y,     // n x 128 (theta1|theta2)
                 int n)
{
    extern __shared__ char smem[];
    uint32_t* Ah32 = (uint32_t*)(smem + OFF_AH);
    uint32_t* Al32 = (uint32_t*)(smem + OFF_AL);
    uint32_t* Bh32 = (uint32_t*)(smem + OFF_BH);
    uint32_t* Bl32 = (uint32_t*)(smem + OFF_BL);

    const int tid = threadIdx.x;
    const int w = tid >> 5;
    const int lane = tid & 31;
    const int mw = w & 7;          // m16 row-group index
    const int nh = w >> 3;         // n half (0: cols 0-31, 1: cols 32-63)
    const int q = lane & 3;
    const int rowBase = blockIdx.x * 128;

    // ---- Convert A rows to bf16 hi/lo in smem (coalesced, conflict-free) --
    for (int f = tid; f < 128 * 96; f += 512) {
        int r = f / 96, k2 = f % 96;
        int gr = rowBase + r;
        float2 v = make_float2(0.f, 0.f);
        if (gr < n) v = *(const float2*)(A + (size_t)gr * DIM + 2 * k2);
        __nv_bfloat162 hh = __floats2bfloat162_rn(v.x, v.y);
        float r0 = v.x - __low2float(hh);
        float r1 = v.y - __high2float(hh);
        __nv_bfloat162 ll = __floats2bfloat162_rn(r0, r1);
        Ah32[r * 100 + k2] = *(uint32_t*)&hh;
        Al32[r * 100 + k2] = *(uint32_t*)&ll;
    }

    // ---- per-lane ldmatrix base addresses (byte addresses in shared) ----
    const uint32_t sb = smem_to_u32(smem);
    // A x4: lanes 0-7 m0(r+0,k+0), 8-15 m1(r+8,k+0), 16-23 m2(r+0,k+8), 24-31 m3(r+8,k+8)
    const int raA = (lane & 7) + ((lane >> 3) & 1) * 8;
    const int kaA = ((lane >> 4) & 1) * 8;
    uint32_t aAh = sb + OFF_AH + (uint32_t)((mw * 16 + raA) * A_STRIDE + kaA) * 2;
    uint32_t aAl = aAh + (OFF_AL - OFF_AH);
    // B x4 over a tile pair: m0(t0,k+0), m1(t0,k+8), m2(t1,k+0), m3(t1,k+8)
    const int rbB = (lane & 7) + ((lane >> 4) & 1) * 8;
    const int kbB = ((lane >> 3) & 1) * 8;
    uint32_t aB0h = sb + OFF_BH + (uint32_t)((nh * 32 + rbB) * A_STRIDE + kbB) * 2;
    uint32_t aB1h = aB0h + 16 * A_STRIDE * 2;
    uint32_t aB0l = aB0h + (OFF_BL - OFF_BH);
    uint32_t aB1l = aB1h + (OFF_BL - OFF_BH);

    const int row0 = rowBase + mw * 16 + (lane >> 2);
    const int row1 = row0 + 8;

#pragma unroll
    for (int tt = 0; tt < 3; ++tt) {
        __syncthreads();   // previous theta's B readers done (and A ready)
        {
            const uint32_t* gh = g_Bh32 + tt * 6144;
            const uint32_t* gl = g_Bl32 + tt * 6144;
            for (int f = tid; f < 64 * 96; f += 512) {
                int nn = f / 96, k2 = f % 96;
                Bh32[nn * 100 + k2] = gh[f];
                Bl32[nn * 100 + k2] = gl[f];
            }
        }
        __syncthreads();

        float4 c0 = make_float4(0.f, 0.f, 0.f, 0.f), c1 = c0, c2 = c0, c3 = c0;

#pragma unroll 2
        for (int ks = 0; ks < 12; ++ks) {
            const uint32_t ko = (uint32_t)ks * 32;   // 16 bf16 = 32 bytes
            uint32_t ah0, ah1, ah2, ah3, al0, al1, al2, al3;
            LDMX4(ah0, ah1, ah2, ah3, aAh + ko);
            LDMX4(al0, al1, al2, al3, aAl + ko);

            uint32_t b0h0, b0h1, b1h0, b1h1;         // pair 0: tiles 0,1
            LDMX4(b0h0, b0h1, b1h0, b1h1, aB0h + ko);
            uint32_t b0l0, b0l1, b1l0, b1l1;
            LDMX4(b0l0, b0l1, b1l0, b1l1, aB0l + ko);
            MMA(c0, ah0, ah1, ah2, ah3, b0h0, b0h1);
            MMA(c0, ah0, ah1, ah2, ah3, b0l0, b0l1);
            MMA(c0, al0, al1, al2, al3, b0h0, b0h1);
            MMA(c1, ah0, ah1, ah2, ah3, b1h0, b1h1);
            MMA(c1, ah0, ah1, ah2, ah3, b1l0, b1l1);
            MMA(c1, al0, al1, al2, al3, b1h0, b1h1);

            uint32_t b2h0, b2h1, b3h0, b3h1;         // pair 1: tiles 2,3
            LDMX4(b2h0, b2h1, b3h0, b3h1, aB1h + ko);
            uint32_t b2l0, b2l1, b3l0, b3l1;
            LDMX4(b2l0, b2l1, b3l0, b3l1, aB1l + ko);
            MMA(c2, ah0, ah1, ah2, ah3, b2h0, b2h1);
            MMA(c2, ah0, ah1, ah2, ah3, b2l0, b2l1);
            MMA(c2, al0, al1, al2, al3, b2h0, b2h1);
            MMA(c3, ah0, ah1, ah2, ah3, b3h0, b3h1);
            MMA(c3, ah0, ah1, ah2, ah3, b3l0, b3l1);
            MMA(c3, al0, al1, al2, al3, b3h0, b3h1);
        }

        // ---- Epilogue for this theta ----
        float* outp = (tt == 0) ? dst : Y;
        const int ostr = (tt == 0) ? DIM : 128;
        const int cb = ((tt == 2) ? 64 : 0) + nh * 32;
#define ST_TILE(C, J)                                                         \
        {                                                                     \
            int col = cb + (J) * 8 + 2 * q;                                   \
            if (row0 < n)                                                     \
                *(float2*)(outp + (size_t)row0 * ostr + col) =                \
                    make_float2(C.x, C.y);                                    \
            if (row1 < n)                                                     \
                *(float2*)(outp + (size_t)row1 * ostr + col) =                \
                    make_float2(C.z, C.w);                                    \
        }
        ST_TILE(c0, 0) ST_TILE(c1, 1) ST_TILE(c2, 2) ST_TILE(c3, 3)
#undef ST_TILE
    }
}

// ---- Aggregation: warp per node, atomic-free CSR gather -------------------
__global__ void agg_kernel(const float* __restrict__ Y, float* __restrict__ dst, int n)
{
    int gw = (blockIdx.x * blockDim.x + threadIdx.x) >> 5;
    int lane = threadIdx.x & 31;
    if (gw >= n) return;
#pragma unroll
    for (int l = 0; l < 2; ++l) {
        const int* rs = g_rowstart + l * (NMAX + 1);
        const int* cs = g_cols + l * EMAX;
        int s = __ldg(rs + gw);
        int e = __ldg(rs + gw + 1);
        const float* Yb = Y + l * 64 + lane * 2;
        float ax = 0.f, ay = 0.f;
        int j = s;
        for (; j + 4 <= e; j += 4) {
            int c0 = cs[j], c1 = cs[j + 1], c2 = cs[j + 2], c3 = cs[j + 3];
            float2 v0 = *(const float2*)(Yb + (size_t)c0 * 128);
            float2 v1 = *(const float2*)(Yb + (size_t)c1 * 128);
            float2 v2 = *(const float2*)(Yb + (size_t)c2 * 128);
            float2 v3 = *(const float2*)(Yb + (size_t)c3 * 128);
            ax += (v0.x + v1.x) + (v2.x + v3.x);
            ay += (v0.y + v1.y) + (v2.y + v3.y);
        }
        for (; j < e; ++j) {
            float2 v = *(const float2*)(Yb + (size_t)cs[j] * 128);
            ax += v.x; ay += v.y;
        }
        float2 o = make_float2(ax, ay);
        *(float2*)(dst + (size_t)gw * DIM + 64 + l * 64 + lane * 2) = o;
    }
}

// ---------------------------------------------------------------------------
extern "C" void kernel_launch(void* const* d_in, const int* in_sizes, int n_in,
                              void* d_out, int out_size)
{
    const float* emb = (const float*)d_in[0];
    const float* t1  = (const float*)d_in[1];
    const float* t2  = (const float*)d_in[2];
    const float* t3  = (const float*)d_in[3];
    const int*   e0  = (const int*)d_in[4];
    const int*   e1  = (const int*)d_in[5];

    int n  = in_sizes[0] / DIM;
    int nE = in_sizes[4] / 2;
    float* out = (float*)d_out;

    void *p_emb1_v, *p_Y_v;
    cudaGetSymbolAddress(&p_emb1_v, g_emb1);
    cudaGetSymbolAddress(&p_Y_v, g_Y);
    float* p_emb1 = (float*)p_emb1_v;
    float* p_Y    = (float*)p_Y_v;

    cudaFuncSetAttribute(gemm_kernel, cudaFuncAttributeMaxDynamicSharedMemorySize,
                         GEMM_SMEM_BYTES);

    int nb = (n + 511) / 512;
    int gemm_blocks = (n + 127) / 128;
    int agg_blocks = (n * 32 + 255) / 256;

    // gemm1 at launch slot #4 (the slot ncu captures) for profiling.
    zero_counts_kernel<<<(2 * NMAX + 255) / 256, 256>>>();                 // 1
    hist_kernel<<<(2 * nE + 255) / 256, 256>>>(e0, e1, nE);                // 2
    convert_theta_kernel<<<(3 * 64 * 96 + 255) / 256, 256>>>(t1, t2, t3);  // 3
    gemm_kernel<<<gemm_blocks, 512, GEMM_SMEM_BYTES>>>(emb, p_emb1, p_Y, n); // 4
    dim3 gscan(nb, 2);
    scan_partial_kernel<<<gscan, 512>>>(n);                                // 5
    dim3 goff((n + 255) / 256, 2);
    add_offsets_kernel<<<goff, 256>>>(n, nb);                              // 6
    fill_kernel<<<(2 * nE + 255) / 256, 256>>>(e0, e1, nE);                // 7
    agg_kernel<<<agg_blocks, 256>>>(p_Y, p_emb1, n);                       // 8
    gemm_kernel<<<gemm_blocks, 512, GEMM_SMEM_BYTES>>>(p_emb1, out, p_Y, n); // 9
    agg_kernel<<<agg_blocks, 256>>>(p_Y, out, n);                          // 10
}